// round 2
// baseline (speedup 1.0000x reference)
#include <cuda_runtime.h>
#include <math.h>

#define B_   8
#define N_   16384
#define S_   512
#define K_   32
#define NPOS_ (B_*S_*K_)   /* 131072 */

// ---------------- scratch (static device memory; no allocations) ----------------
__device__ float  g_nsum[B_*N_];
__device__ int    g_fps [B_*S_];
__device__ float  g_nx[B_*S_], g_ny[B_*S_], g_nz[B_*S_], g_ssum[B_*S_];
__device__ int    g_group[NPOS_];
__device__ float  g_y1[NPOS_*64];
__device__ float  g_y2[NPOS_*64];
__device__ float  g_y3[(size_t)NPOS_*128];
__device__ double g_s1[64], g_q1[64], g_s2[64], g_q2[64], g_s3[128], g_q3[128];
__device__ float  g_A1[64], g_B1[64], g_A2[64], g_B2[64], g_A3[128], g_B3[128];

// ---------------- zero BN accumulators (graph replays need re-zero) -------------
__global__ void zero_kernel(){
    int i = threadIdx.x;
    if (i < 64){ g_s1[i]=0.0; g_q1[i]=0.0; g_s2[i]=0.0; g_q2[i]=0.0; }
    if (i < 128){ g_s3[i]=0.0; g_q3[i]=0.0; }
}

// ---------------- per-point |p|^2 ------------------------------------------------
__global__ void nsum_kernel(const float* __restrict__ xyz){
    int t = blockIdx.x*blockDim.x + threadIdx.x;   // 131072 = B_*N_
    int b = t >> 14;
    int n = t & (N_-1);
    const float* p = xyz + (size_t)b*3*N_;
    float x = p[n], y = p[N_+n], z = p[2*N_+n];
    g_nsum[t] = __fmaf_rn(z,z,__fmaf_rn(y,y,__fmul_rn(x,x)));
}

// ---------------- farthest point sampling (1 CTA per batch) ---------------------
__global__ void __launch_bounds__(1024,1) fps_kernel(const float* __restrict__ xyz){
    extern __shared__ float sm[];
    float* sx = sm;
    float* sy = sm + N_;
    float* sz = sm + 2*N_;
    __shared__ float rv[32];
    __shared__ int   ri[32];
    __shared__ int   sFar;

    const int b   = blockIdx.x;
    const int tid = threadIdx.x;
    const float* base = xyz + (size_t)b*3*N_;

    for (int i = tid; i < N_; i += 1024){
        sx[i] = base[i];
        sy[i] = base[N_ + i];
        sz[i] = base[2*N_ + i];
    }
    __syncthreads();

    // cache first 8 of 16 points per thread in registers (halves per-step smem traffic)
    float px[8], py[8], pz[8];
#pragma unroll
    for (int j = 0; j < 8; j++){
        int n = tid + j*1024;
        px[j] = sx[n]; py[j] = sy[n]; pz[j] = sz[n];
    }
    float dist[16];
#pragma unroll
    for (int j = 0; j < 16; j++) dist[j] = 1e10f;

    int far = 0;
    const int lane = tid & 31;
    const int wd   = tid >> 5;

    for (int step = 0; step < S_; ++step){
        if (tid == 0) g_fps[b*S_ + step] = far;

        float cx = sx[far], cy = sy[far], cz = sz[far];
        float best = -1.0f; int bi = 0;
#pragma unroll
        for (int j = 0; j < 8; j++){
            float dx = px[j]-cx, dy = py[j]-cy, dz = pz[j]-cz;
            float d = __fmaf_rn(dz,dz,__fmaf_rn(dy,dy,__fmul_rn(dx,dx)));
            float dm = fminf(dist[j], d);
            dist[j] = dm;
            if (dm > best){ best = dm; bi = tid + j*1024; }
        }
#pragma unroll
        for (int j = 8; j < 16; j++){
            int n = tid + j*1024;
            float dx = sx[n]-cx, dy = sy[n]-cy, dz = sz[n]-cz;
            float d = __fmaf_rn(dz,dz,__fmaf_rn(dy,dy,__fmul_rn(dx,dx)));
            float dm = fminf(dist[j], d);
            dist[j] = dm;
            if (dm > best){ best = dm; bi = n; }
        }
        // warp argmax (ties -> smaller index, matching jnp.argmax first-max semantics)
#pragma unroll
        for (int off = 16; off > 0; off >>= 1){
            float v  = __shfl_down_sync(0xffffffffu, best, off);
            int   ii = __shfl_down_sync(0xffffffffu, bi,   off);
            if (v > best || (v == best && ii < bi)){ best = v; bi = ii; }
        }
        if (lane == 0){ rv[wd] = best; ri[wd] = bi; }
        __syncthreads();
        if (wd == 0){
            best = rv[lane]; bi = ri[lane];
#pragma unroll
            for (int off = 16; off > 0; off >>= 1){
                float v  = __shfl_down_sync(0xffffffffu, best, off);
                int   ii = __shfl_down_sync(0xffffffffu, bi,   off);
                if (v > best || (v == best && ii < bi)){ best = v; bi = ii; }
            }
            if (lane == 0) sFar = bi;
        }
        __syncthreads();
        far = sFar;
    }
}

// ---------------- gather sampled centroids + write new_xyz output ---------------
__global__ void gather_kernel(const float* __restrict__ xyz, float* __restrict__ out){
    int t = blockIdx.x*blockDim.x + threadIdx.x;   // 4096 = B_*S_
    int b = t >> 9, s = t & 511;
    int idx = g_fps[t];
    const float* p = xyz + (size_t)b*3*N_;
    float x = p[idx], y = p[N_+idx], z = p[2*N_+idx];
    g_nx[t] = x; g_ny[t] = y; g_nz[t] = z;
    g_ssum[t] = __fmaf_rn(z,z,__fmaf_rn(y,y,__fmul_rn(x,x)));
    out[(b*3+0)*S_ + s] = x;
    out[(b*3+1)*S_ + s] = y;
    out[(b*3+2)*S_ + s] = z;
}

// ---------------- ball query (1 warp per centroid, in-order compaction) ---------
__global__ void ball_kernel(const float* __restrict__ xyz){
    __shared__ int buf[8][32];
    int tid = threadIdx.x, lane = tid & 31, wl = tid >> 5;
    int w = blockIdx.x*8 + wl;                    // 4096 centroids
    int b = w >> 9;
    const float* xb = xyz + (size_t)b*3*N_;
    const float* ns = g_nsum + b*N_;
    float cx = g_nx[w], cy = g_ny[w], cz = g_nz[w], ss = g_ssum[w];

    int cnt = 0;
    for (int basei = 0; basei < N_; basei += 32){
        int n = basei + lane;
        float x = xb[n], y = xb[N_+n], z = xb[2*N_+n];
        float dot = __fmaf_rn(cz,z,__fmaf_rn(cy,y,__fmul_rn(cx,x)));
        float sq  = __fadd_rn(__fadd_rn(ss, ns[n]), -2.0f*dot);
        bool qv = !(sq > 0.04f);
        unsigned mm = __ballot_sync(0xffffffffu, qv);
        if (qv){
            int pos = cnt + __popc(mm & ((1u<<lane)-1u));
            if (pos < 32) buf[wl][pos] = n;
        }
        cnt += __popc(mm);
        if (cnt >= 32) break;
    }
    __syncwarp();
    int cc = cnt < 32 ? cnt : 32;
    int first = buf[wl][0];
    int v = (lane < cc) ? buf[wl][lane] : first;
    g_group[w*32 + lane] = v;
}

// ---------------- layer 1: gather 6 inputs, 6->64, raw y + channel sums ---------
__global__ void layer1_kernel(const float* __restrict__ xyz, const float* __restrict__ pts,
                              const float* __restrict__ w0, const float* __restrict__ b0){
    int tid = threadIdx.x, lane = tid & 31, wl = tid >> 5;
    int warpG = blockIdx.x*8 + wl;                // 4096 warps
    int o0 = 2*lane, o1 = o0 + 1;
    float wr0[6], wr1[6];
#pragma unroll
    for (int c = 0; c < 6; c++){ wr0[c] = w0[o0*6+c]; wr1[c] = w0[o1*6+c]; }
    float bb0 = b0[o0], bb1 = b0[o1];
    float s0 = 0.f, s1 = 0.f, q0 = 0.f, q1 = 0.f;
    __shared__ float shS[64], shQ[64];
    if (tid < 64){ shS[tid] = 0.f; shQ[tid] = 0.f; }
    __syncthreads();

    for (int p = warpG; p < NPOS_; p += 4096){
        int idx = g_group[p];
        int b = p >> 14;
        int s = (p >> 5) & 511;
        int bs = (b << 9) + s;
        const float* pb = pts + (size_t)b*3*N_;
        const float* xb = xyz + (size_t)b*3*N_;
        float x0 = pb[idx], x1 = pb[N_+idx], x2 = pb[2*N_+idx];
        float x3 = xb[idx]      - g_nx[bs];
        float x4 = xb[N_+idx]   - g_ny[bs];
        float x5 = xb[2*N_+idx] - g_nz[bs];
        float a0 = bb0, a1 = bb1;
        a0 = fmaf(wr0[0],x0,a0); a0 = fmaf(wr0[1],x1,a0); a0 = fmaf(wr0[2],x2,a0);
        a0 = fmaf(wr0[3],x3,a0); a0 = fmaf(wr0[4],x4,a0); a0 = fmaf(wr0[5],x5,a0);
        a1 = fmaf(wr1[0],x0,a1); a1 = fmaf(wr1[1],x1,a1); a1 = fmaf(wr1[2],x2,a1);
        a1 = fmaf(wr1[3],x3,a1); a1 = fmaf(wr1[4],x4,a1); a1 = fmaf(wr1[5],x5,a1);
        *(float2*)&g_y1[(size_t)p*64 + o0] = make_float2(a0, a1);
        s0 += a0; q0 += a0*a0; s1 += a1; q1 += a1*a1;
    }
    atomicAdd(&shS[o0], s0); atomicAdd(&shS[o1], s1);
    atomicAdd(&shQ[o0], q0); atomicAdd(&shQ[o1], q1);
    __syncthreads();
    if (tid < 64){
        atomicAdd(&g_s1[tid], (double)shS[tid]);
        atomicAdd(&g_q1[tid], (double)shQ[tid]);
    }
}

// ---------------- BN finalize: fold into y*A + B ---------------------------------
__global__ void bnfin_kernel(int layer, const float* __restrict__ g, const float* __restrict__ be){
    int i = threadIdx.x;
    const double *s, *q; float *A, *Bv; int C;
    if (layer == 0){ s = g_s1; q = g_q1; A = g_A1; Bv = g_B1; C = 64; }
    else if (layer == 1){ s = g_s2; q = g_q2; A = g_A2; Bv = g_B2; C = 64; }
    else { s = g_s3; q = g_q3; A = g_A3; Bv = g_B3; C = 128; }
    if (i < C){
        double mean = s[i] * (1.0 / (double)NPOS_);
        double var  = q[i] * (1.0 / (double)NPOS_) - mean*mean;
        float rstd = rsqrtf((float)var + 1e-5f);
        float a = rstd * g[i];
        A[i] = a;
        Bv[i] = be[i] - (float)mean * a;
    }
}

// ---------------- layer 2: BN1+ReLU on load, 64->64, raw y + sums ---------------
__global__ void layer2_kernel(const float* __restrict__ w1, const float* __restrict__ b1){
    __shared__ float ws[64*64];
    __shared__ float sc[64], sh[64];
    __shared__ float shS[64], shQ[64];
    int tid = threadIdx.x, lane = tid & 31, wl = tid >> 5;
    for (int i = tid; i < 4096; i += 256){
        int o = i >> 6, k = i & 63;
        ws[k*64 + o] = w1[i];                      // transpose to [k][o]
    }
    if (tid < 64){ sc[tid] = g_A1[tid]; sh[tid] = g_B1[tid]; shS[tid] = 0.f; shQ[tid] = 0.f; }
    __syncthreads();

    int warpG = blockIdx.x*8 + wl;
    int o0 = 2*lane;
    float bb0 = b1[o0], bb1 = b1[o0+1];
    float sc0 = sc[lane], sh0 = sh[lane], sc1 = sc[lane+32], sh1 = sh[lane+32];
    float s0 = 0.f, s1 = 0.f, q0 = 0.f, q1 = 0.f;

    for (int p = warpG; p < NPOS_; p += 4096){
        float v0 = fmaxf(fmaf(g_y1[(size_t)p*64 + lane],      sc0, sh0), 0.f);
        float v1 = fmaxf(fmaf(g_y1[(size_t)p*64 + lane + 32], sc1, sh1), 0.f);
        float a0 = bb0, a1 = bb1;
#pragma unroll
        for (int kk = 0; kk < 32; kk++){
            float xk = __shfl_sync(0xffffffffu, v0, kk);
            float2 wv = *(const float2*)&ws[kk*64 + o0];
            a0 = fmaf(wv.x, xk, a0); a1 = fmaf(wv.y, xk, a1);
        }
#pragma unroll
        for (int kk = 0; kk < 32; kk++){
            float xk = __shfl_sync(0xffffffffu, v1, kk);
            float2 wv = *(const float2*)&ws[(kk+32)*64 + o0];
            a0 = fmaf(wv.x, xk, a0); a1 = fmaf(wv.y, xk, a1);
        }
        *(float2*)&g_y2[(size_t)p*64 + o0] = make_float2(a0, a1);
        s0 += a0; q0 += a0*a0; s1 += a1; q1 += a1*a1;
    }
    atomicAdd(&shS[o0], s0); atomicAdd(&shS[o0+1], s1);
    atomicAdd(&shQ[o0], q0); atomicAdd(&shQ[o0+1], q1);
    __syncthreads();
    if (tid < 64){
        atomicAdd(&g_s2[tid], (double)shS[tid]);
        atomicAdd(&g_q2[tid], (double)shQ[tid]);
    }
}

// ---------------- layer 3: BN2+ReLU on load, 64->128, raw y + sums --------------
__global__ void layer3_kernel(const float* __restrict__ w2, const float* __restrict__ b2){
    __shared__ float ws[64*128];
    __shared__ float sc[64], sh[64];
    __shared__ float shS[128], shQ[128];
    int tid = threadIdx.x, lane = tid & 31, wl = tid >> 5;
    for (int i = tid; i < 8192; i += 256){
        int o = i >> 6, k = i & 63;
        ws[k*128 + o] = w2[i];
    }
    if (tid < 64){ sc[tid] = g_A2[tid]; sh[tid] = g_B2[tid]; }
    if (tid < 128){ shS[tid] = 0.f; shQ[tid] = 0.f; }
    __syncthreads();

    int warpG = blockIdx.x*8 + wl;
    int o0 = 4*lane;
    float bb[4];
#pragma unroll
    for (int j = 0; j < 4; j++) bb[j] = b2[o0+j];
    float sc0 = sc[lane], sh0 = sh[lane], sc1 = sc[lane+32], sh1 = sh[lane+32];
    float sa[4] = {0.f,0.f,0.f,0.f}, qa[4] = {0.f,0.f,0.f,0.f};

    for (int p = warpG; p < NPOS_; p += 4096){
        float v0 = fmaxf(fmaf(g_y2[(size_t)p*64 + lane],      sc0, sh0), 0.f);
        float v1 = fmaxf(fmaf(g_y2[(size_t)p*64 + lane + 32], sc1, sh1), 0.f);
        float a0 = bb[0], a1 = bb[1], a2 = bb[2], a3 = bb[3];
#pragma unroll
        for (int kk = 0; kk < 32; kk++){
            float xk = __shfl_sync(0xffffffffu, v0, kk);
            float4 wv = *(const float4*)&ws[kk*128 + o0];
            a0 = fmaf(wv.x, xk, a0); a1 = fmaf(wv.y, xk, a1);
            a2 = fmaf(wv.z, xk, a2); a3 = fmaf(wv.w, xk, a3);
        }
#pragma unroll
        for (int kk = 0; kk < 32; kk++){
            float xk = __shfl_sync(0xffffffffu, v1, kk);
            float4 wv = *(const float4*)&ws[(kk+32)*128 + o0];
            a0 = fmaf(wv.x, xk, a0); a1 = fmaf(wv.y, xk, a1);
            a2 = fmaf(wv.z, xk, a2); a3 = fmaf(wv.w, xk, a3);
        }
        *(float4*)&g_y3[(size_t)p*128 + o0] = make_float4(a0, a1, a2, a3);
        sa[0] += a0; qa[0] += a0*a0; sa[1] += a1; qa[1] += a1*a1;
        sa[2] += a2; qa[2] += a2*a2; sa[3] += a3; qa[3] += a3*a3;
    }
#pragma unroll
    for (int j = 0; j < 4; j++){
        atomicAdd(&shS[o0+j], sa[j]);
        atomicAdd(&shQ[o0+j], qa[j]);
    }
    __syncthreads();
    if (tid < 128){
        atomicAdd(&g_s3[tid], (double)shS[tid]);
        atomicAdd(&g_q3[tid], (double)shQ[tid]);
    }
}

// ---------------- BN3 + ReLU + max over K, write new_feat -----------------------
__global__ void pool_kernel(float* __restrict__ out){
    int tid = threadIdx.x, lane = tid & 31, wl = tid >> 5;
    int w = blockIdx.x*8 + wl;                    // (b,s), 4096 total
    int b = w >> 9, s = w & 511;
    float A[4], Bv[4];
#pragma unroll
    for (int j = 0; j < 4; j++){ A[j] = g_A3[lane + 32*j]; Bv[j] = g_B3[lane + 32*j]; }
    float m[4] = {-1e30f, -1e30f, -1e30f, -1e30f};
    const float* base = g_y3 + (size_t)w*K_*128;
    for (int k = 0; k < K_; k++){
        const float* row = base + k*128;
#pragma unroll
        for (int j = 0; j < 4; j++){
            float v = fmaxf(fmaf(row[lane + 32*j], A[j], Bv[j]), 0.f);
            m[j] = fmaxf(m[j], v);
        }
    }
    float* fout = out + B_*3*S_;                  // after new_xyz (12288 floats)
#pragma unroll
    for (int j = 0; j < 4; j++)
        fout[((b << 7) + lane + 32*j)*S_ + s] = m[j];
}

// ---------------- launch ---------------------------------------------------------
extern "C" void kernel_launch(void* const* d_in, const int* in_sizes, int n_in,
                              void* d_out, int out_size){
    const float* xyz = (const float*)d_in[0];
    const float* pts = (const float*)d_in[1];
    const float* w0  = (const float*)d_in[2];
    const float* b0  = (const float*)d_in[3];
    const float* g0  = (const float*)d_in[4];
    const float* be0 = (const float*)d_in[5];
    const float* w1  = (const float*)d_in[6];
    const float* b1  = (const float*)d_in[7];
    const float* g1  = (const float*)d_in[8];
    const float* be1 = (const float*)d_in[9];
    const float* w2  = (const float*)d_in[10];
    const float* b2  = (const float*)d_in[11];
    const float* g2  = (const float*)d_in[12];
    const float* be2 = (const float*)d_in[13];
    float* out = (float*)d_out;

    cudaFuncSetAttribute(fps_kernel, cudaFuncAttributeMaxDynamicSharedMemorySize, 3*N_*4);

    zero_kernel  <<<1, 128>>>();
    nsum_kernel  <<<512, 256>>>(xyz);
    fps_kernel   <<<B_, 1024, 3*N_*4>>>(xyz);
    gather_kernel<<<16, 256>>>(xyz, out);
    ball_kernel  <<<512, 256>>>(xyz);
    layer1_kernel<<<512, 256>>>(xyz, pts, w0, b0);
    bnfin_kernel <<<1, 128>>>(0, g0, be0);
    layer2_kernel<<<512, 256>>>(w1, b1);
    bnfin_kernel <<<1, 128>>>(1, g1, be1);
    layer3_kernel<<<512, 256>>>(w2, b2);
    bnfin_kernel <<<1, 128>>>(2, g2, be2);
    pool_kernel  <<<512, 256>>>(out);
}